// round 1
// baseline (speedup 1.0000x reference)
#include <cuda_runtime.h>
#include <cstdint>

#define BATCH  8
#define LTOK   4096
#define DIMC   384
#define DIN    768
#define DSTATE 64
#define DTRANK 24
#define HIDC   1536
#define MROWS  (BATCH*LTOK)   // 32768
#define XDBW   152            // DT_RANK + 2*D_STATE

// ---------------- scratch (static device memory; no allocation allowed) ----
__device__ float g_xn [ (size_t)MROWS*DIMC ];   // 50 MB  (LN output, reused for LN2)
__device__ float g_xz [ (size_t)MROWS*1536 ];   // 201 MB (xr | z)
__device__ float g_xc [ (size_t)MROWS*DIN  ];   // 100 MB (conv+silu)
__device__ float g_xdb[ (size_t)MROWS*XDBW ];   // 20 MB  (dt_raw | B | C)
__device__ float g_dt [ (size_t)MROWS*DIN  ];   // 100 MB
__device__ float g_y  [ (size_t)MROWS*DIN  ];   // 100 MB (scan out, gated)
__device__ float g_x2 [ (size_t)MROWS*DIMC ];   // 50 MB  (x + mamba)
__device__ float g_f1 [ (size_t)MROWS*HIDC ];   // 201 MB
__device__ float g_f2 [ (size_t)MROWS*HIDC ];   // 201 MB

// ---------------- LayerNorm: one warp per row of 384 ------------------------
__global__ void ln_kernel(const float* __restrict__ x, const float* __restrict__ g,
                          const float* __restrict__ b, float* __restrict__ out) {
    int row  = blockIdx.x * 8 + (threadIdx.x >> 5);
    int lane = threadIdx.x & 31;
    const float* xr = x + (size_t)row * DIMC;
    float v[12];
    float s = 0.f;
#pragma unroll
    for (int i = 0; i < 12; i++) { v[i] = xr[lane + 32*i]; s += v[i]; }
#pragma unroll
    for (int o = 16; o; o >>= 1) s += __shfl_xor_sync(~0u, s, o);
    float mu = s * (1.0f/DIMC);
    float q = 0.f;
#pragma unroll
    for (int i = 0; i < 12; i++) { float d = v[i]-mu; q += d*d; }
#pragma unroll
    for (int o = 16; o; o >>= 1) q += __shfl_xor_sync(~0u, q, o);
    float rs = rsqrtf(q*(1.0f/DIMC) + 1e-5f);
    float* orow = out + (size_t)row * DIMC;
#pragma unroll
    for (int i = 0; i < 12; i++) {
        int c = lane + 32*i;
        orow[c] = (v[i]-mu)*rs*g[c] + b[c];
    }
}

// ---------------- SGEMM: C[M,N] = A[M,K] * B[N,K]^T (+bias)(+res) ------------
// BM=128, BN=64, BK=16, 256 threads, 8x4 per thread.
// EPI: bit0 = add bias[col], bit1 = add res[row*N+col]
template<int EPI>
__global__ void __launch_bounds__(256)
sgemm_kernel(const float* __restrict__ A, const float* __restrict__ B,
             float* __restrict__ C, const float* __restrict__ bias,
             const float* __restrict__ res, int M, int N, int K) {
    __shared__ float As[16][128];
    __shared__ float Bs[16][64];
    int tid = threadIdx.x;
    int m0 = blockIdx.y * 128;
    int n0 = blockIdx.x * 64;
    float acc[8][4];
#pragma unroll
    for (int i = 0; i < 8; i++)
#pragma unroll
        for (int j = 0; j < 4; j++) acc[i][j] = 0.f;

    int txn = (tid & 15) * 4;
    int tym = (tid >> 4) * 8;

    for (int k0 = 0; k0 < K; k0 += 16) {
        // A tile: 128x16 = 512 float4, 2 per thread
#pragma unroll
        for (int i = 0; i < 2; i++) {
            int id = tid + i*256;
            int m = id >> 2, kq = id & 3;
            float4 a = *(const float4*)(A + (size_t)(m0+m)*K + k0 + kq*4);
            As[kq*4+0][m] = a.x; As[kq*4+1][m] = a.y;
            As[kq*4+2][m] = a.z; As[kq*4+3][m] = a.w;
        }
        // B tile: 64x16 = 256 float4, 1 per thread (guard N)
        {
            int n = tid >> 2, kq = tid & 3;
            float4 bv = make_float4(0.f,0.f,0.f,0.f);
            if (n0 + n < N)
                bv = *(const float4*)(B + (size_t)(n0+n)*K + k0 + kq*4);
            Bs[kq*4+0][n] = bv.x; Bs[kq*4+1][n] = bv.y;
            Bs[kq*4+2][n] = bv.z; Bs[kq*4+3][n] = bv.w;
        }
        __syncthreads();
#pragma unroll
        for (int kk = 0; kk < 16; kk++) {
            float aa[8], bb[4];
            *(float4*)bb     = *(const float4*)&Bs[kk][txn];
            *(float4*)aa     = *(const float4*)&As[kk][tym];
            *(float4*)(aa+4) = *(const float4*)&As[kk][tym+4];
#pragma unroll
            for (int i = 0; i < 8; i++)
#pragma unroll
                for (int j = 0; j < 4; j++)
                    acc[i][j] = fmaf(aa[i], bb[j], acc[i][j]);
        }
        __syncthreads();
    }
#pragma unroll
    for (int i = 0; i < 8; i++) {
        int row = m0 + tym + i;
#pragma unroll
        for (int j = 0; j < 4; j++) {
            int col = n0 + txn + j;
            if (col < N) {
                float v = acc[i][j];
                if (EPI & 1) v += bias[col];
                if (EPI & 2) v += res[(size_t)row*N + col];
                C[(size_t)row*N + col] = v;
            }
        }
    }
}

// ---------------- causal depthwise conv1d (width 4) + SiLU ------------------
__global__ void conv_silu_kernel(const float* __restrict__ xz, const float* __restrict__ cw,
                                 const float* __restrict__ cb, float* __restrict__ xc) {
    int idx = blockIdx.x * 256 + threadIdx.x;       // over MROWS*DIN
    int d   = idx % DIN;
    int row = idx / DIN;                            // b*LTOK + t
    int t   = row % LTOK;
    float acc = cb[d];
#pragma unroll
    for (int k = 0; k < 4; k++) {
        int tt = t + k - 3;
        if (tt >= 0)
            acc += xz[(size_t)(row + k - 3)*1536 + d] * cw[d*4 + k];
    }
    xc[idx] = acc / (1.f + __expf(-acc));           // silu
}

// ---------------- dt = softplus(xdb[:,:24] @ W_dt^T + b_dt) -----------------
__global__ void dt_kernel(const float* __restrict__ xdb, const float* __restrict__ Wdt,
                          const float* __restrict__ bdt, float* __restrict__ dt) {
    __shared__ float s[DTRANK];
    int i = blockIdx.x;
    if (threadIdx.x < DTRANK) s[threadIdx.x] = xdb[(size_t)i*XDBW + threadIdx.x];
    __syncthreads();
    for (int d = threadIdx.x; d < DIN; d += 256) {
        float acc = bdt[d];
#pragma unroll
        for (int k = 0; k < DTRANK; k++) acc += s[k] * Wdt[d*DTRANK + k];
        dt[(size_t)i*DIN + d] = (acc > 20.f) ? acc : log1pf(expf(acc));
    }
}

// ---------------- selective scan: one warp per (b, channel), 2 states/lane --
__global__ void scan_kernel(const float* __restrict__ dtp, const float* __restrict__ xc,
                            const float* __restrict__ xz,  const float* __restrict__ xdb,
                            const float* __restrict__ A_log, const float* __restrict__ Dp,
                            float* __restrict__ y) {
    int warp = threadIdx.x >> 5;
    int lane = threadIdx.x & 31;
    int gb = blockIdx.x;                  // 0..(BATCH*DIN/4 - 1)
    int b  = gb / (DIN/4);
    int d  = (gb % (DIN/4)) * 4 + warp;
    float A1 = -expf(A_log[d*DSTATE + lane]);
    float A2 = -expf(A_log[d*DSTATE + lane + 32]);
    float Dpd = Dp[d];
    float h1 = 0.f, h2 = 0.f;
    size_t base = (size_t)b * LTOK;
    for (int t = 0; t < LTOK; t++) {
        size_t r = base + t;
        float dtv = dtp[r*DIN + d];
        float xv  = xc [r*DIN + d];
        float zv  = xz [r*1536 + DIN + d];
        const float* xrow = xdb + r*XDBW;
        float B1 = xrow[DTRANK + lane],          B2 = xrow[DTRANK + lane + 32];
        float C1 = xrow[DTRANK + DSTATE + lane], C2 = xrow[DTRANK + DSTATE + lane + 32];
        float dA1 = __expf(dtv * A1);
        float dA2 = __expf(dtv * A2);
        float dtx = dtv * xv;
        h1 = h1*dA1 + dtx*B1;
        h2 = h2*dA2 + dtx*B2;
        float p = h1*C1 + h2*C2;
#pragma unroll
        for (int o = 16; o; o >>= 1) p += __shfl_xor_sync(~0u, p, o);
        if (lane == 0) {
            float yv = p + xv*Dpd;
            yv *= zv / (1.f + __expf(-zv));   // * silu(z)
            y[r*DIN + d] = yv;
        }
    }
}

// ---------------- 3x3 depthwise conv on 64x64 grid + exact GELU -------------
__global__ void dwconv_gelu_kernel(const float* __restrict__ f, const float* __restrict__ w,
                                   const float* __restrict__ bias, float* __restrict__ out) {
    int idx = blockIdx.x * 256 + threadIdx.x;   // over MROWS*HID
    int d = idx % HIDC;
    int n = (idx / HIDC) % LTOK;
    int b = idx / (HIDC * LTOK);
    int r = n >> 6, c = n & 63;
    float acc = bias[d];
#pragma unroll
    for (int i = 0; i < 3; i++) {
        int rr = r + i - 1;
        if ((unsigned)rr < 64u) {
#pragma unroll
            for (int j = 0; j < 3; j++) {
                int cc = c + j - 1;
                if ((unsigned)cc < 64u)
                    acc += f[((size_t)b*LTOK + rr*64 + cc)*HIDC + d] * w[d*9 + i*3 + j];
            }
        }
    }
    out[idx] = 0.5f * acc * (1.f + erff(acc * 0.7071067811865476f));
}

// ---------------- launch --------------------------------------------------
extern "C" void kernel_launch(void* const* d_in, const int* in_sizes, int n_in,
                              void* d_out, int out_size) {
    const float* x      = (const float*)d_in[0];
    const float* gamma1 = (const float*)d_in[3];
    const float* beta1  = (const float*)d_in[4];
    const float* W_in   = (const float*)d_in[5];
    const float* conv_w = (const float*)d_in[6];
    const float* conv_b = (const float*)d_in[7];
    const float* W_xprj = (const float*)d_in[8];
    const float* W_dt   = (const float*)d_in[9];
    const float* b_dt   = (const float*)d_in[10];
    const float* A_log  = (const float*)d_in[11];
    const float* Dp     = (const float*)d_in[12];
    const float* W_out  = (const float*)d_in[13];
    const float* gamma2 = (const float*)d_in[14];
    const float* beta2  = (const float*)d_in[15];
    const float* W1     = (const float*)d_in[16];
    const float* b1     = (const float*)d_in[17];
    const float* dw_w   = (const float*)d_in[18];
    const float* dw_b   = (const float*)d_in[19];
    const float* W2     = (const float*)d_in[20];
    const float* b2     = (const float*)d_in[21];

    float *xn, *xz, *xc, *xdb, *dt, *y, *x2, *f1, *f2;
    cudaGetSymbolAddress((void**)&xn,  g_xn);
    cudaGetSymbolAddress((void**)&xz,  g_xz);
    cudaGetSymbolAddress((void**)&xc,  g_xc);
    cudaGetSymbolAddress((void**)&xdb, g_xdb);
    cudaGetSymbolAddress((void**)&dt,  g_dt);
    cudaGetSymbolAddress((void**)&y,   g_y);
    cudaGetSymbolAddress((void**)&x2,  g_x2);
    cudaGetSymbolAddress((void**)&f1,  g_f1);
    cudaGetSymbolAddress((void**)&f2,  g_f2);

    // 1) xn = LN(x)
    ln_kernel<<<MROWS/8, 256>>>(x, gamma1, beta1, xn);
    // 2) xz = xn @ W_in^T    (M=32768, N=1536, K=384)
    { dim3 g(1536/64, MROWS/128);
      sgemm_kernel<0><<<g, 256>>>(xn, W_in, xz, nullptr, nullptr, MROWS, 1536, DIMC); }
    // 3) xc = silu(causal_conv1d(xr) + conv_b)
    conv_silu_kernel<<<(MROWS*DIN)/256, 256>>>(xz, conv_w, conv_b, xc);
    // 4) xdb = xc @ W_xproj^T  (N=152, K=768)
    { dim3 g((XDBW + 63)/64, MROWS/128);
      sgemm_kernel<0><<<g, 256>>>(xc, W_xprj, xdb, nullptr, nullptr, MROWS, XDBW, DIN); }
    // 5) dt = softplus(xdb[:, :24] @ W_dt^T + b_dt)
    dt_kernel<<<MROWS, 256>>>(xdb, W_dt, b_dt, dt);
    // 6) selective scan + D skip + silu(z) gate -> y
    scan_kernel<<<(BATCH*DIN)/4, 128>>>(dt, xc, xz, xdb, A_log, Dp, y);
    // 7) x2 = x + y @ W_out^T  (N=384, K=768)
    { dim3 g(DIMC/64, MROWS/128);
      sgemm_kernel<2><<<g, 256>>>(y, W_out, x2, nullptr, x, MROWS, DIMC, DIN); }
    // 8) xn = LN(x2)
    ln_kernel<<<MROWS/8, 256>>>(x2, gamma2, beta2, xn);
    // 9) f1 = xn @ W1^T + b1   (N=1536, K=384)
    { dim3 g(HIDC/64, MROWS/128);
      sgemm_kernel<1><<<g, 256>>>(xn, W1, f1, b1, nullptr, MROWS, HIDC, DIMC); }
    // 10) f2 = gelu(dwconv3x3(f1) + dw_b)
    dwconv_gelu_kernel<<<(MROWS*HIDC)/256, 256>>>(f1, dw_w, dw_b, f2);
    // 11) out = x2 + f2 @ W2^T + b2  (N=384, K=1536)
    { dim3 g(DIMC/64, MROWS/128);
      sgemm_kernel<3><<<g, 256>>>(f2, W2, (float*)d_out, b2, x2, MROWS, DIMC, HIDC); }
}

// round 5
// speedup vs baseline: 1.2224x; 1.2224x over previous
#include <cuda_runtime.h>
#include <cuda_bf16.h>
#include <cstdint>

#define BATCH  8
#define LTOK   4096
#define DIMC   384
#define DIN    768
#define DSTATE 64
#define DTRANK 24
#define HIDC   1536
#define MROWS  (BATCH*LTOK)   // 32768
#define XDBW   152            // DT_RANK + 2*D_STATE

// ---------------- scratch (static device memory; no allocation allowed) ----
__device__ float g_xn [ (size_t)MROWS*DIMC ];
__device__ float g_xz [ (size_t)MROWS*1536 ];
__device__ float g_xc [ (size_t)MROWS*DIN  ];
__device__ float g_xdb[ (size_t)MROWS*XDBW ];
__device__ float g_dt [ (size_t)MROWS*DIN  ];
__device__ float g_y  [ (size_t)MROWS*DIN  ];
__device__ float g_x2 [ (size_t)MROWS*DIMC ];
__device__ float g_f1 [ (size_t)MROWS*HIDC ];
__device__ float g_f2 [ (size_t)MROWS*HIDC ];

// ---------------- LayerNorm: one warp per row of 384 ------------------------
__global__ void ln_kernel(const float* __restrict__ x, const float* __restrict__ g,
                          const float* __restrict__ b, float* __restrict__ out) {
    int row  = blockIdx.x * 8 + (threadIdx.x >> 5);
    int lane = threadIdx.x & 31;
    const float* xr = x + (size_t)row * DIMC;
    float v[12];
    float s = 0.f;
#pragma unroll
    for (int i = 0; i < 12; i++) { v[i] = xr[lane + 32*i]; s += v[i]; }
#pragma unroll
    for (int o = 16; o; o >>= 1) s += __shfl_xor_sync(~0u, s, o);
    float mu = s * (1.0f/DIMC);
    float q = 0.f;
#pragma unroll
    for (int i = 0; i < 12; i++) { float d = v[i]-mu; q += d*d; }
#pragma unroll
    for (int o = 16; o; o >>= 1) q += __shfl_xor_sync(~0u, q, o);
    float rs = rsqrtf(q*(1.0f/DIMC) + 1e-5f);
    float* orow = out + (size_t)row * DIMC;
#pragma unroll
    for (int i = 0; i < 12; i++) {
        int c = lane + 32*i;
        orow[c] = (v[i]-mu)*rs*g[c] + b[c];
    }
}

// =====================================================================
// Tensor-core GEMM: C[M,N] = A[M,K] @ B[N,K]^T, fp32 in/out,
// bf16 split (hi+lo), 3-pass mma.sync m16n8k16.
// BM=128, BN=64, BK=32. 256 threads = 8 warps (2x4), warp tile 64x16.
// Requires M%128==0, N%64==0, K%32==0.
// EPI: bit0 = +bias[col], bit1 = +res[row*N+col]
// =====================================================================
#define AST 40   // smem row stride in halves (conflict-free for ldmatrix)

__device__ __forceinline__ uint32_t pack_hi(float a, float b, float& ra, float& rb) {
    __nv_bfloat16 ha = __float2bfloat16(a);
    __nv_bfloat16 hb = __float2bfloat16(b);
    ra = a - __bfloat162float(ha);   // exact residual in fp32
    rb = b - __bfloat162float(hb);
    uint16_t ua = *(uint16_t*)&ha, ub = *(uint16_t*)&hb;
    return ((uint32_t)ub << 16) | ua;
}
__device__ __forceinline__ uint32_t pack_only(float a, float b) {
    __nv_bfloat16 ha = __float2bfloat16(a);
    __nv_bfloat16 hb = __float2bfloat16(b);
    uint16_t ua = *(uint16_t*)&ha, ub = *(uint16_t*)&hb;
    return ((uint32_t)ub << 16) | ua;
}

__device__ __forceinline__ void ldsm4(uint32_t r[4], uint32_t addr) {
    asm volatile("ldmatrix.sync.aligned.m8n8.x4.shared.b16 {%0,%1,%2,%3}, [%4];"
        : "=r"(r[0]), "=r"(r[1]), "=r"(r[2]), "=r"(r[3]) : "r"(addr));
}
__device__ __forceinline__ void mma16816(float c[4], const uint32_t a[4],
                                         uint32_t b0, uint32_t b1) {
    asm volatile("mma.sync.aligned.m16n8k16.row.col.f32.bf16.bf16.f32 "
        "{%0,%1,%2,%3}, {%4,%5,%6,%7}, {%8,%9}, {%0,%1,%2,%3};"
        : "+f"(c[0]), "+f"(c[1]), "+f"(c[2]), "+f"(c[3])
        : "r"(a[0]), "r"(a[1]), "r"(a[2]), "r"(a[3]), "r"(b0), "r"(b1));
}

template<int EPI>
__global__ void __launch_bounds__(256, 2)
mma_gemm_kernel(const float* __restrict__ A, const float* __restrict__ B,
                float* __restrict__ C, const float* __restrict__ bias,
                const float* __restrict__ res, int M, int N, int K) {
    __shared__ __nv_bfloat16 sAhi[128*AST];
    __shared__ __nv_bfloat16 sAlo[128*AST];
    __shared__ __nv_bfloat16 sBhi[64*AST];
    __shared__ __nv_bfloat16 sBlo[64*AST];

    const int tid  = threadIdx.x;
    const int lane = tid & 31, warp = tid >> 5;
    const int wm = warp >> 2, wn = warp & 3;     // 2 x 4 warp grid
    const int m0 = blockIdx.y * 128;
    const int n0 = blockIdx.x * 64;

    // global load mapping
    const int row_a = tid >> 1;            // 0..127
    const int ksegA = (tid & 1) * 16;      // 16 consecutive k
    const int row_b = tid >> 2;            // 0..63
    const int ksegB = (tid & 3) * 8;       // 8 consecutive k

    float regA[16], regB[8];

    const uint32_t baseAhi = (uint32_t)__cvta_generic_to_shared(sAhi);
    const uint32_t baseAlo = (uint32_t)__cvta_generic_to_shared(sAlo);
    const uint32_t baseBhi = (uint32_t)__cvta_generic_to_shared(sBhi);
    const uint32_t baseBlo = (uint32_t)__cvta_generic_to_shared(sBlo);

    float acc[4][2][4];
#pragma unroll
    for (int i = 0; i < 4; i++)
#pragma unroll
        for (int j = 0; j < 2; j++)
#pragma unroll
            for (int t = 0; t < 4; t++) acc[i][j][t] = 0.f;

    const int iters = K / 32;

    // prologue load
    {
        const float* pa = A + (size_t)(m0 + row_a) * K + ksegA;
#pragma unroll
        for (int q = 0; q < 4; q++) *(float4*)&regA[q*4] = *(const float4*)(pa + q*4);
        const float* pb = B + (size_t)(n0 + row_b) * K + ksegB;
#pragma unroll
        for (int q = 0; q < 2; q++) *(float4*)&regB[q*4] = *(const float4*)(pb + q*4);
    }

    for (int it = 0; it < iters; ++it) {
        // STS: convert fp32 regs -> hi/lo bf16, 16B packed stores
        {
            uint32_t ph[4], pl[4];
            float rl[8];
            // A first 8 floats -> [row_a][ksegA .. +7]
#pragma unroll
            for (int q = 0; q < 4; q++) ph[q] = pack_hi(regA[q*2], regA[q*2+1], rl[q*2], rl[q*2+1]);
#pragma unroll
            for (int q = 0; q < 4; q++) pl[q] = pack_only(rl[q*2], rl[q*2+1]);
            *(uint4*)&sAhi[row_a*AST + ksegA] = make_uint4(ph[0], ph[1], ph[2], ph[3]);
            *(uint4*)&sAlo[row_a*AST + ksegA] = make_uint4(pl[0], pl[1], pl[2], pl[3]);
            // A next 8 floats -> [row_a][ksegA+8 .. +15]
#pragma unroll
            for (int q = 0; q < 4; q++) ph[q] = pack_hi(regA[8+q*2], regA[8+q*2+1], rl[q*2], rl[q*2+1]);
#pragma unroll
            for (int q = 0; q < 4; q++) pl[q] = pack_only(rl[q*2], rl[q*2+1]);
            *(uint4*)&sAhi[row_a*AST + ksegA + 8] = make_uint4(ph[0], ph[1], ph[2], ph[3]);
            *(uint4*)&sAlo[row_a*AST + ksegA + 8] = make_uint4(pl[0], pl[1], pl[2], pl[3]);
            // B 8 floats -> [row_b][ksegB .. +7]
#pragma unroll
            for (int q = 0; q < 4; q++) ph[q] = pack_hi(regB[q*2], regB[q*2+1], rl[q*2], rl[q*2+1]);
#pragma unroll
            for (int q = 0; q < 4; q++) pl[q] = pack_only(rl[q*2], rl[q*2+1]);
            *(uint4*)&sBhi[row_b*AST + ksegB] = make_uint4(ph[0], ph[1], ph[2], ph[3]);
            *(uint4*)&sBlo[row_b*AST + ksegB] = make_uint4(pl[0], pl[1], pl[2], pl[3]);
        }
        __syncthreads();

        // prefetch next tile into regs (hidden under MMA below)
        if (it + 1 < iters) {
            const int kb = (it + 1) * 32;
            const float* pa = A + (size_t)(m0 + row_a) * K + kb + ksegA;
#pragma unroll
            for (int q = 0; q < 4; q++) *(float4*)&regA[q*4] = *(const float4*)(pa + q*4);
            const float* pb = B + (size_t)(n0 + row_b) * K + kb + ksegB;
#pragma unroll
            for (int q = 0; q < 2; q++) *(float4*)&regB[q*4] = *(const float4*)(pb + q*4);
        }

        // compute: 2 k16 steps, 3 passes (hi*hi, hi*lo, lo*hi)
#pragma unroll
        for (int s = 0; s < 2; s++) {
            const int kk = s * 16;
            uint32_t Ah[4][4], Al[4][4], Bh[4], Bl[4];
            const int arow_off = (lane & 15);
            const int acol = kk + ((lane >> 4) * 8);
#pragma unroll
            for (int mf = 0; mf < 4; mf++) {
                uint32_t off = (uint32_t)((wm*64 + mf*16 + arow_off) * AST + acol) * 2;
                ldsm4(Ah[mf], baseAhi + off);
                ldsm4(Al[mf], baseAlo + off);
            }
            {
                const int brow = wn*16 + (lane & 7) + ((lane >> 4) * 8);
                const int bcol = kk + (((lane >> 3) & 1) * 8);
                uint32_t off = (uint32_t)(brow * AST + bcol) * 2;
                ldsm4(Bh, baseBhi + off);
                ldsm4(Bl, baseBlo + off);
            }
#pragma unroll
            for (int mf = 0; mf < 4; mf++) {
                mma16816(acc[mf][0], Ah[mf], Bh[0], Bh[1]);
                mma16816(acc[mf][1], Ah[mf], Bh[2], Bh[3]);
                mma16816(acc[mf][0], Ah[mf], Bl[0], Bl[1]);
                mma16816(acc[mf][1], Ah[mf], Bl[2], Bl[3]);
                mma16816(acc[mf][0], Al[mf], Bh[0], Bh[1]);
                mma16816(acc[mf][1], Al[mf], Bh[2], Bh[3]);
            }
        }
        __syncthreads();
    }

    // epilogue
    const int g = lane >> 2, tc = lane & 3;
#pragma unroll
    for (int mf = 0; mf < 4; mf++) {
#pragma unroll
        for (int nf = 0; nf < 2; nf++) {
            int col = n0 + wn*16 + nf*8 + tc*2;
            float b0 = 0.f, b1 = 0.f;
            if (EPI & 1) { b0 = bias[col]; b1 = bias[col+1]; }
#pragma unroll
            for (int half = 0; half < 2; half++) {
                int row = m0 + wm*64 + mf*16 + g + half*8;
                float v0 = acc[mf][nf][half*2]   + b0;
                float v1 = acc[mf][nf][half*2+1] + b1;
                if (EPI & 2) {
                    const float2 r = *(const float2*)(res + (size_t)row*N + col);
                    v0 += r.x; v1 += r.y;
                }
                *(float2*)(C + (size_t)row*N + col) = make_float2(v0, v1);
            }
        }
    }
}

// ---------------- fp32 SGEMM kept for N=152 (xproj) -------------------------
template<int EPI>
__global__ void __launch_bounds__(256)
sgemm_kernel(const float* __restrict__ A, const float* __restrict__ B,
             float* __restrict__ C, const float* __restrict__ bias,
             const float* __restrict__ res, int M, int N, int K) {
    __shared__ float As[16][128];
    __shared__ float Bs[16][64];
    int tid = threadIdx.x;
    int m0 = blockIdx.y * 128;
    int n0 = blockIdx.x * 64;
    float acc[8][4];
#pragma unroll
    for (int i = 0; i < 8; i++)
#pragma unroll
        for (int j = 0; j < 4; j++) acc[i][j] = 0.f;

    int txn = (tid & 15) * 4;
    int tym = (tid >> 4) * 8;

    for (int k0 = 0; k0 < K; k0 += 16) {
#pragma unroll
        for (int i = 0; i < 2; i++) {
            int id = tid + i*256;
            int m = id >> 2, kq = id & 3;
            float4 a = *(const float4*)(A + (size_t)(m0+m)*K + k0 + kq*4);
            As[kq*4+0][m] = a.x; As[kq*4+1][m] = a.y;
            As[kq*4+2][m] = a.z; As[kq*4+3][m] = a.w;
        }
        {
            int n = tid >> 2, kq = tid & 3;
            float4 bv = make_float4(0.f,0.f,0.f,0.f);
            if (n0 + n < N)
                bv = *(const float4*)(B + (size_t)(n0+n)*K + k0 + kq*4);
            Bs[kq*4+0][n] = bv.x; Bs[kq*4+1][n] = bv.y;
            Bs[kq*4+2][n] = bv.z; Bs[kq*4+3][n] = bv.w;
        }
        __syncthreads();
#pragma unroll
        for (int kk = 0; kk < 16; kk++) {
            float aa[8], bb[4];
            *(float4*)bb     = *(const float4*)&Bs[kk][txn];
            *(float4*)aa     = *(const float4*)&As[kk][tym];
            *(float4*)(aa+4) = *(const float4*)&As[kk][tym+4];
#pragma unroll
            for (int i = 0; i < 8; i++)
#pragma unroll
                for (int j = 0; j < 4; j++)
                    acc[i][j] = fmaf(aa[i], bb[j], acc[i][j]);
        }
        __syncthreads();
    }
#pragma unroll
    for (int i = 0; i < 8; i++) {
        int row = m0 + tym + i;
#pragma unroll
        for (int j = 0; j < 4; j++) {
            int col = n0 + txn + j;
            if (col < N) {
                float v = acc[i][j];
                if (EPI & 1) v += bias[col];
                if (EPI & 2) v += res[(size_t)row*N + col];
                C[(size_t)row*N + col] = v;
            }
        }
    }
}

// ---------------- causal depthwise conv1d (width 4) + SiLU ------------------
__global__ void conv_silu_kernel(const float* __restrict__ xz, const float* __restrict__ cw,
                                 const float* __restrict__ cb, float* __restrict__ xc) {
    int idx = blockIdx.x * 256 + threadIdx.x;
    int d   = idx % DIN;
    int row = idx / DIN;
    int t   = row % LTOK;
    float acc = cb[d];
#pragma unroll
    for (int k = 0; k < 4; k++) {
        int tt = t + k - 3;
        if (tt >= 0)
            acc += xz[(size_t)(row + k - 3)*1536 + d] * cw[d*4 + k];
    }
    xc[idx] = acc / (1.f + __expf(-acc));
}

// ---------------- dt = softplus(xdb[:,:24] @ W_dt^T + b_dt) -----------------
__global__ void dt_kernel(const float* __restrict__ xdb, const float* __restrict__ Wdt,
                          const float* __restrict__ bdt, float* __restrict__ dt) {
    __shared__ float s[DTRANK];
    int i = blockIdx.x;
    if (threadIdx.x < DTRANK) s[threadIdx.x] = xdb[(size_t)i*XDBW + threadIdx.x];
    __syncthreads();
    for (int d = threadIdx.x; d < DIN; d += 256) {
        float acc = bdt[d];
#pragma unroll
        for (int k = 0; k < DTRANK; k++) acc += s[k] * Wdt[d*DTRANK + k];
        dt[(size_t)i*DIN + d] = (acc > 20.f) ? acc : log1pf(expf(acc));
    }
}

// ---------------- selective scan: one warp per (b, channel), 2 states/lane --
__global__ void scan_kernel(const float* __restrict__ dtp, const float* __restrict__ xc,
                            const float* __restrict__ xz,  const float* __restrict__ xdb,
                            const float* __restrict__ A_log, const float* __restrict__ Dp,
                            float* __restrict__ y) {
    int warp = threadIdx.x >> 5;
    int lane = threadIdx.x & 31;
    int gb = blockIdx.x;
    int b  = gb / (DIN/4);
    int d  = (gb % (DIN/4)) * 4 + warp;
    float A1 = -expf(A_log[d*DSTATE + lane]);
    float A2 = -expf(A_log[d*DSTATE + lane + 32]);
    float Dpd = Dp[d];
    float h1 = 0.f, h2 = 0.f;
    size_t base = (size_t)b * LTOK;
    for (int t = 0; t < LTOK; t++) {
        size_t r = base + t;
        float dtv = dtp[r*DIN + d];
        float xv  = xc [r*DIN + d];
        float zv  = xz [r*1536 + DIN + d];
        const float* xrow = xdb + r*XDBW;
        float B1 = xrow[DTRANK + lane],          B2 = xrow[DTRANK + lane + 32];
        float C1 = xrow[DTRANK + DSTATE + lane], C2 = xrow[DTRANK + DSTATE + lane + 32];
        float dA1 = __expf(dtv * A1);
        float dA2 = __expf(dtv * A2);
        float dtx = dtv * xv;
        h1 = h1*dA1 + dtx*B1;
        h2 = h2*dA2 + dtx*B2;
        float p = h1*C1 + h2*C2;
#pragma unroll
        for (int o = 16; o; o >>= 1) p += __shfl_xor_sync(~0u, p, o);
        if (lane == 0) {
            float yv = p + xv*Dpd;
            yv *= zv / (1.f + __expf(-zv));
            y[r*DIN + d] = yv;
        }
    }
}

// ---------------- 3x3 depthwise conv on 64x64 grid + exact GELU -------------
__global__ void dwconv_gelu_kernel(const float* __restrict__ f, const float* __restrict__ w,
                                   const float* __restrict__ bias, float* __restrict__ out) {
    int idx = blockIdx.x * 256 + threadIdx.x;
    int d = idx % HIDC;
    int n = (idx / HIDC) % LTOK;
    int b = idx / (HIDC * LTOK);
    int r = n >> 6, c = n & 63;
    float acc = bias[d];
#pragma unroll
    for (int i = 0; i < 3; i++) {
        int rr = r + i - 1;
        if ((unsigned)rr < 64u) {
#pragma unroll
            for (int j = 0; j < 3; j++) {
                int cc = c + j - 1;
                if ((unsigned)cc < 64u)
                    acc += f[((size_t)b*LTOK + rr*64 + cc)*HIDC + d] * w[d*9 + i*3 + j];
            }
        }
    }
    out[idx] = 0.5f * acc * (1.f + erff(acc * 0.7071067811865476f));
}

// ---------------- launch --------------------------------------------------
extern "C" void kernel_launch(void* const* d_in, const int* in_sizes, int n_in,
                              void* d_out, int out_size) {
    const float* x      = (const float*)d_in[0];
    const float* gamma1 = (const float*)d_in[3];
    const float* beta1  = (const float*)d_in[4];
    const float* W_in   = (const float*)d_in[5];
    const float* conv_w = (const float*)d_in[6];
    const float* conv_b = (const float*)d_in[7];
    const float* W_xprj = (const float*)d_in[8];
    const float* W_dt   = (const float*)d_in[9];
    const float* b_dt   = (const float*)d_in[10];
    const float* A_log  = (const float*)d_in[11];
    const float* Dp     = (const float*)d_in[12];
    const float* W_out  = (const float*)d_in[13];
    const float* gamma2 = (const float*)d_in[14];
    const float* beta2  = (const float*)d_in[15];
    const float* W1     = (const float*)d_in[16];
    const float* b1     = (const float*)d_in[17];
    const float* dw_w   = (const float*)d_in[18];
    const float* dw_b   = (const float*)d_in[19];
    const float* W2     = (const float*)d_in[20];
    const float* b2     = (const float*)d_in[21];

    float *xn, *xz, *xc, *xdb, *dt, *y, *x2, *f1, *f2;
    cudaGetSymbolAddress((void**)&xn,  g_xn);
    cudaGetSymbolAddress((void**)&xz,  g_xz);
    cudaGetSymbolAddress((void**)&xc,  g_xc);
    cudaGetSymbolAddress((void**)&xdb, g_xdb);
    cudaGetSymbolAddress((void**)&dt,  g_dt);
    cudaGetSymbolAddress((void**)&y,   g_y);
    cudaGetSymbolAddress((void**)&x2,  g_x2);
    cudaGetSymbolAddress((void**)&f1,  g_f1);
    cudaGetSymbolAddress((void**)&f2,  g_f2);

    // 1) xn = LN(x)
    ln_kernel<<<MROWS/8, 256>>>(x, gamma1, beta1, xn);
    // 2) xz = xn @ W_in^T    (M=32768, N=1536, K=384)  [tensor core]
    { dim3 g(1536/64, MROWS/128);
      mma_gemm_kernel<0><<<g, 256>>>(xn, W_in, xz, nullptr, nullptr, MROWS, 1536, DIMC); }
    // 3) xc = silu(causal_conv1d(xr) + conv_b)
    conv_silu_kernel<<<(MROWS*DIN)/256, 256>>>(xz, conv_w, conv_b, xc);
    // 4) xdb = xc @ W_xproj^T  (N=152, K=768)  [fp32 fallback]
    { dim3 g((XDBW + 63)/64, MROWS/128);
      sgemm_kernel<0><<<g, 256>>>(xc, W_xprj, xdb, nullptr, nullptr, MROWS, XDBW, DIN); }
    // 5) dt = softplus(xdb[:, :24] @ W_dt^T + b_dt)
    dt_kernel<<<MROWS, 256>>>(xdb, W_dt, b_dt, dt);
    // 6) selective scan + D skip + silu(z) gate -> y
    scan_kernel<<<(BATCH*DIN)/4, 128>>>(dt, xc, xz, xdb, A_log, Dp, y);
    // 7) x2 = x + y @ W_out^T  (N=384, K=768)  [tensor core]
    { dim3 g(DIMC/64, MROWS/128);
      mma_gemm_kernel<2><<<g, 256>>>(y, W_out, x2, nullptr, x, MROWS, DIMC, DIN); }
    // 8) xn = LN(x2)
    ln_kernel<<<MROWS/8, 256>>>(x2, gamma2, beta2, xn);
    // 9) f1 = xn @ W1^T + b1   (N=1536, K=384)  [tensor core]
    { dim3 g(HIDC/64, MROWS/128);
      mma_gemm_kernel<1><<<g, 256>>>(xn, W1, f1, b1, nullptr, MROWS, HIDC, DIMC); }
    // 10) f2 = gelu(dwconv3x3(f1) + dw_b)
    dwconv_gelu_kernel<<<(MROWS*HIDC)/256, 256>>>(f1, dw_w, dw_b, f2);
    // 11) out = x2 + f2 @ W2^T + b2  (N=384, K=1536)  [tensor core]
    { dim3 g(DIMC/64, MROWS/128);
      mma_gemm_kernel<3><<<g, 256>>>(f2, W2, (float*)d_out, b2, x2, MROWS, DIMC, HIDC); }
}

// round 6
// speedup vs baseline: 1.2630x; 1.0332x over previous
#include <cuda_runtime.h>
#include <cuda_bf16.h>
#include <cstdint>

#define BATCH  8
#define LTOK   4096
#define DIMC   384
#define DIN    768
#define DSTATE 64
#define DTRANK 24
#define HIDC   1536
#define MROWS  (BATCH*LTOK)   // 32768
#define XDBP   192            // padded xproj width (152 -> 192)

typedef __nv_bfloat16 bf16;

// ---------------- scratch (static device memory) ---------------------------
__device__ float g_xz [ (size_t)MROWS*1536 ];
__device__ float g_xc [ (size_t)MROWS*DIN  ];
__device__ float g_xdb[ (size_t)MROWS*XDBP ];
__device__ float g_dt [ (size_t)MROWS*DIN  ];
__device__ float g_x2 [ (size_t)MROWS*DIMC ];
__device__ float g_f1 [ (size_t)MROWS*HIDC ];

__device__ alignas(16) bf16 g_xnh[ (size_t)MROWS*DIMC ];
__device__ alignas(16) bf16 g_xnl[ (size_t)MROWS*DIMC ];
__device__ alignas(16) bf16 g_xch[ (size_t)MROWS*DIN  ];
__device__ alignas(16) bf16 g_xcl[ (size_t)MROWS*DIN  ];
__device__ alignas(16) bf16 g_yh [ (size_t)MROWS*DIN  ];
__device__ alignas(16) bf16 g_yl [ (size_t)MROWS*DIN  ];
__device__ alignas(16) bf16 g_f2h[ (size_t)MROWS*HIDC ];
__device__ alignas(16) bf16 g_f2l[ (size_t)MROWS*HIDC ];

// weights hi/lo
__device__ alignas(16) bf16 g_winh[1536*384], g_winl[1536*384];
__device__ alignas(16) bf16 g_wxh [XDBP*768], g_wxl [XDBP*768];
__device__ alignas(16) bf16 g_woh [384*768],  g_wol [384*768];
__device__ alignas(16) bf16 g_w1h [1536*384], g_w1l [1536*384];
__device__ alignas(16) bf16 g_w2h [384*1536], g_w2l [384*1536];

__device__ __forceinline__ void split_bf16(float v, bf16& h, bf16& l) {
    h = __float2bfloat16(v);
    l = __float2bfloat16(v - __bfloat162float(h));
}

// ---------------- weight fp32 -> bf16 hi/lo --------------------------------
__global__ void wconv_kernel(const float* __restrict__ W, bf16* __restrict__ wh,
                             bf16* __restrict__ wl, int n) {
    int i = blockIdx.x * 256 + threadIdx.x;
    if (i < n) { bf16 h, l; split_bf16(W[i], h, l); wh[i] = h; wl[i] = l; }
}
// padded xproj weight: rows 152..191 zero
__global__ void wconv_pad_kernel(const float* __restrict__ W, bf16* __restrict__ wh,
                                 bf16* __restrict__ wl) {
    int i = blockIdx.x * 256 + threadIdx.x;   // over XDBP*768
    if (i >= XDBP*768) return;
    int row = i / 768, col = i % 768;
    float v = (row < 152) ? W[row*768 + col] : 0.f;
    bf16 h, l; split_bf16(v, h, l); wh[i] = h; wl[i] = l;
}

// ---------------- LayerNorm -> bf16 hi/lo ----------------------------------
__global__ void ln_bf16_kernel(const float* __restrict__ x, const float* __restrict__ g,
                               const float* __restrict__ b, bf16* __restrict__ oh,
                               bf16* __restrict__ ol) {
    int row  = blockIdx.x * 8 + (threadIdx.x >> 5);
    int lane = threadIdx.x & 31;
    const float* xr = x + (size_t)row * DIMC;
    float v[12];
    float s = 0.f;
#pragma unroll
    for (int i = 0; i < 12; i++) { v[i] = xr[lane + 32*i]; s += v[i]; }
#pragma unroll
    for (int o = 16; o; o >>= 1) s += __shfl_xor_sync(~0u, s, o);
    float mu = s * (1.0f/DIMC);
    float q = 0.f;
#pragma unroll
    for (int i = 0; i < 12; i++) { float d = v[i]-mu; q += d*d; }
#pragma unroll
    for (int o = 16; o; o >>= 1) q += __shfl_xor_sync(~0u, q, o);
    float rs = rsqrtf(q*(1.0f/DIMC) + 1e-5f);
#pragma unroll
    for (int i = 0; i < 12; i++) {
        int c = lane + 32*i;
        float o = (v[i]-mu)*rs*g[c] + b[c];
        bf16 h, l; split_bf16(o, h, l);
        oh[(size_t)row*DIMC + c] = h;
        ol[(size_t)row*DIMC + c] = l;
    }
}

// =====================================================================
// bf16 split GEMM: C[M,N] = (Ah+Al)[M,K] @ (Bh+Bl)[N,K]^T (3-pass),
// cp.async double-buffered. BM=128, BN=64, BK=32. 256 thr = 8 warps (2x4).
// EPI: bit0 = +bias[col], bit1 = +res[row*N+col]
// =====================================================================
#define AST 40          // smem row stride in halves (80B, odd 16B units)
#define STG 15360       // halves per stage: A 2*5120 + B 2*2560
#define SM_BYTES (2*STG*2)

__device__ __forceinline__ void cp16(uint32_t dst, const void* src) {
    asm volatile("cp.async.cg.shared.global [%0], [%1], 16;" :: "r"(dst), "l"(src));
}
__device__ __forceinline__ void ldsm4(uint32_t r[4], uint32_t addr) {
    asm volatile("ldmatrix.sync.aligned.m8n8.x4.shared.b16 {%0,%1,%2,%3}, [%4];"
        : "=r"(r[0]), "=r"(r[1]), "=r"(r[2]), "=r"(r[3]) : "r"(addr));
}
__device__ __forceinline__ void mma16816(float c[4], const uint32_t a[4],
                                         uint32_t b0, uint32_t b1) {
    asm volatile("mma.sync.aligned.m16n8k16.row.col.f32.bf16.bf16.f32 "
        "{%0,%1,%2,%3}, {%4,%5,%6,%7}, {%8,%9}, {%0,%1,%2,%3};"
        : "+f"(c[0]), "+f"(c[1]), "+f"(c[2]), "+f"(c[3])
        : "r"(a[0]), "r"(a[1]), "r"(a[2]), "r"(a[3]), "r"(b0), "r"(b1));
}

template<int EPI>
__global__ void __launch_bounds__(256, 2)
bgemm_kernel(const bf16* __restrict__ Ah, const bf16* __restrict__ Al,
             const bf16* __restrict__ Bh, const bf16* __restrict__ Bl,
             float* __restrict__ C, const float* __restrict__ bias,
             const float* __restrict__ res, int M, int N, int K) {
    extern __shared__ bf16 sm[];
    const uint32_t base = (uint32_t)__cvta_generic_to_shared(sm);

    const int tid  = threadIdx.x;
    const int lane = tid & 31, warp = tid >> 5;
    const int wm = warp >> 2, wn = warp & 3;
    const int m0 = blockIdx.y * 128;
    const int n0 = blockIdx.x * 64;

    float acc[4][2][4];
#pragma unroll
    for (int i = 0; i < 4; i++)
#pragma unroll
        for (int j = 0; j < 2; j++)
#pragma unroll
            for (int t = 0; t < 4; t++) acc[i][j][t] = 0.f;

    const int iters = K / 32;

    // cp.async producer mapping
    const int ra0 = (tid*2) >> 2,  ka0 = (tid*2) & 3;       // A chunk 0
    const int ra1 = (tid*2+1) >> 2, ka1 = (tid*2+1) & 3;    // A chunk 1
    const int rb  = tid >> 2,       kb  = tid & 3;          // B chunk

    auto issue = [&](int it, int s) {
        const int k0 = it * 32;
        uint32_t sb = base + (uint32_t)(s*STG)*2;
        // A hi
        cp16(sb + (ra0*AST + ka0*8)*2,        Ah + (size_t)(m0+ra0)*K + k0 + ka0*8);
        cp16(sb + (ra1*AST + ka1*8)*2,        Ah + (size_t)(m0+ra1)*K + k0 + ka1*8);
        // A lo
        cp16(sb + (5120 + ra0*AST + ka0*8)*2, Al + (size_t)(m0+ra0)*K + k0 + ka0*8);
        cp16(sb + (5120 + ra1*AST + ka1*8)*2, Al + (size_t)(m0+ra1)*K + k0 + ka1*8);
        // B hi / lo
        cp16(sb + (10240 + rb*AST + kb*8)*2,  Bh + (size_t)(n0+rb)*K + k0 + kb*8);
        cp16(sb + (12800 + rb*AST + kb*8)*2,  Bl + (size_t)(n0+rb)*K + k0 + kb*8);
        asm volatile("cp.async.commit_group;");
    };

    issue(0, 0);

    for (int it = 0; it < iters; ++it) {
        if (it + 1 < iters) {
            issue(it + 1, (it + 1) & 1);
            asm volatile("cp.async.wait_group 1;");
        } else {
            asm volatile("cp.async.wait_group 0;");
        }
        __syncthreads();

        const int s = it & 1;
        const uint32_t bAh = base + (uint32_t)(s*STG)*2;
        const uint32_t bAl = bAh + 5120*2;
        const uint32_t bBh = bAh + 10240*2;
        const uint32_t bBl = bAh + 12800*2;

#pragma unroll
        for (int st = 0; st < 2; st++) {
            const int kk = st * 16;
            uint32_t Ahf[4][4], Alf[4][4], Bhf[4], Blf[4];
            const int arow = (lane & 15);
            const int acol = kk + ((lane >> 4) * 8);
#pragma unroll
            for (int mf = 0; mf < 4; mf++) {
                uint32_t off = (uint32_t)((wm*64 + mf*16 + arow) * AST + acol) * 2;
                ldsm4(Ahf[mf], bAh + off);
                ldsm4(Alf[mf], bAl + off);
            }
            {
                const int brow = wn*16 + (lane & 7) + ((lane >> 4) * 8);
                const int bcol = kk + (((lane >> 3) & 1) * 8);
                uint32_t off = (uint32_t)(brow * AST + bcol) * 2;
                ldsm4(Bhf, bBh + off);
                ldsm4(Blf, bBl + off);
            }
#pragma unroll
            for (int mf = 0; mf < 4; mf++) {
                mma16816(acc[mf][0], Ahf[mf], Bhf[0], Bhf[1]);
                mma16816(acc[mf][1], Ahf[mf], Bhf[2], Bhf[3]);
                mma16816(acc[mf][0], Ahf[mf], Blf[0], Blf[1]);
                mma16816(acc[mf][1], Ahf[mf], Blf[2], Blf[3]);
                mma16816(acc[mf][0], Alf[mf], Bhf[0], Bhf[1]);
                mma16816(acc[mf][1], Alf[mf], Bhf[2], Bhf[3]);
            }
        }
        __syncthreads();
    }

    // epilogue
    const int g = lane >> 2, tc = lane & 3;
#pragma unroll
    for (int mf = 0; mf < 4; mf++) {
#pragma unroll
        for (int nf = 0; nf < 2; nf++) {
            int col = n0 + wn*16 + nf*8 + tc*2;
            float b0 = 0.f, b1 = 0.f;
            if (EPI & 1) { b0 = bias[col]; b1 = bias[col+1]; }
#pragma unroll
            for (int half = 0; half < 2; half++) {
                int row = m0 + wm*64 + mf*16 + g + half*8;
                float v0 = acc[mf][nf][half*2]   + b0;
                float v1 = acc[mf][nf][half*2+1] + b1;
                if (EPI & 2) {
                    const float2 r = *(const float2*)(res + (size_t)row*N + col);
                    v0 += r.x; v1 += r.y;
                }
                *(float2*)(C + (size_t)row*N + col) = make_float2(v0, v1);
            }
        }
    }
}

// ---------------- causal depthwise conv1d (width 4) + SiLU ------------------
__global__ void conv_silu_kernel(const float* __restrict__ xz, const float* __restrict__ cw,
                                 const float* __restrict__ cb, float* __restrict__ xc,
                                 bf16* __restrict__ xch, bf16* __restrict__ xcl) {
    int idx = blockIdx.x * 256 + threadIdx.x;
    int d   = idx % DIN;
    int row = idx / DIN;
    int t   = row % LTOK;
    float acc = cb[d];
#pragma unroll
    for (int k = 0; k < 4; k++) {
        int tt = t + k - 3;
        if (tt >= 0)
            acc += xz[(size_t)(row + k - 3)*1536 + d] * cw[d*4 + k];
    }
    float s = acc / (1.f + __expf(-acc));
    xc[idx] = s;
    bf16 h, l; split_bf16(s, h, l);
    xch[idx] = h; xcl[idx] = l;
}

// ---------------- dt = softplus(xdb[:,:24] @ W_dt^T + b_dt) -----------------
__global__ void dt_kernel(const float* __restrict__ xdb, const float* __restrict__ Wdt,
                          const float* __restrict__ bdt, float* __restrict__ dt) {
    __shared__ float s[DTRANK];
    int i = blockIdx.x;
    if (threadIdx.x < DTRANK) s[threadIdx.x] = xdb[(size_t)i*XDBP + threadIdx.x];
    __syncthreads();
    for (int d = threadIdx.x; d < DIN; d += 256) {
        float acc = bdt[d];
#pragma unroll
        for (int k = 0; k < DTRANK; k++) acc += s[k] * Wdt[d*DTRANK + k];
        dt[(size_t)i*DIN + d] = (acc > 20.f) ? acc : log1pf(expf(acc));
    }
}

// ---------------- selective scan: one warp per (b, channel) -----------------
__global__ void scan_kernel(const float* __restrict__ dtp, const float* __restrict__ xc,
                            const float* __restrict__ xz,  const float* __restrict__ xdb,
                            const float* __restrict__ A_log, const float* __restrict__ Dp,
                            bf16* __restrict__ yh, bf16* __restrict__ yl) {
    int warp = threadIdx.x >> 5;
    int lane = threadIdx.x & 31;
    int gb = blockIdx.x;
    int b  = gb / (DIN/4);
    int d  = (gb % (DIN/4)) * 4 + warp;
    float A1 = -expf(A_log[d*DSTATE + lane]);
    float A2 = -expf(A_log[d*DSTATE + lane + 32]);
    float Dpd = Dp[d];
    float h1 = 0.f, h2 = 0.f;
    size_t base = (size_t)b * LTOK;
    for (int t = 0; t < LTOK; t++) {
        size_t r = base + t;
        float dtv = dtp[r*DIN + d];
        float xv  = xc [r*DIN + d];
        float zv  = xz [r*1536 + DIN + d];
        const float* xrow = xdb + r*XDBP;
        float B1 = xrow[DTRANK + lane],          B2 = xrow[DTRANK + lane + 32];
        float C1 = xrow[DTRANK + DSTATE + lane], C2 = xrow[DTRANK + DSTATE + lane + 32];
        float dA1 = __expf(dtv * A1);
        float dA2 = __expf(dtv * A2);
        float dtx = dtv * xv;
        h1 = h1*dA1 + dtx*B1;
        h2 = h2*dA2 + dtx*B2;
        float p = h1*C1 + h2*C2;
#pragma unroll
        for (int o = 16; o; o >>= 1) p += __shfl_xor_sync(~0u, p, o);
        if (lane == 0) {
            float yv = p + xv*Dpd;
            yv *= zv / (1.f + __expf(-zv));
            bf16 hh, ll; split_bf16(yv, hh, ll);
            yh[r*DIN + d] = hh; yl[r*DIN + d] = ll;
        }
    }
}

// ---------------- 3x3 depthwise conv on 64x64 grid + exact GELU -------------
__global__ void dwconv_gelu_kernel(const float* __restrict__ f, const float* __restrict__ w,
                                   const float* __restrict__ bias,
                                   bf16* __restrict__ oh, bf16* __restrict__ ol) {
    int idx = blockIdx.x * 256 + threadIdx.x;
    int d = idx % HIDC;
    int n = (idx / HIDC) % LTOK;
    int b = idx / (HIDC * LTOK);
    int r = n >> 6, c = n & 63;
    float acc = bias[d];
#pragma unroll
    for (int i = 0; i < 3; i++) {
        int rr = r + i - 1;
        if ((unsigned)rr < 64u) {
#pragma unroll
            for (int j = 0; j < 3; j++) {
                int cc = c + j - 1;
                if ((unsigned)cc < 64u)
                    acc += f[((size_t)b*LTOK + rr*64 + cc)*HIDC + d] * w[d*9 + i*3 + j];
            }
        }
    }
    float g = 0.5f * acc * (1.f + erff(acc * 0.7071067811865476f));
    bf16 h, l; split_bf16(g, h, l);
    oh[idx] = h; ol[idx] = l;
}

// ---------------- launch --------------------------------------------------
extern "C" void kernel_launch(void* const* d_in, const int* in_sizes, int n_in,
                              void* d_out, int out_size) {
    const float* x      = (const float*)d_in[0];
    const float* gamma1 = (const float*)d_in[3];
    const float* beta1  = (const float*)d_in[4];
    const float* W_in   = (const float*)d_in[5];
    const float* conv_w = (const float*)d_in[6];
    const float* conv_b = (const float*)d_in[7];
    const float* W_xprj = (const float*)d_in[8];
    const float* W_dt   = (const float*)d_in[9];
    const float* b_dt   = (const float*)d_in[10];
    const float* A_log  = (const float*)d_in[11];
    const float* Dp     = (const float*)d_in[12];
    const float* W_out  = (const float*)d_in[13];
    const float* gamma2 = (const float*)d_in[14];
    const float* beta2  = (const float*)d_in[15];
    const float* W1     = (const float*)d_in[16];
    const float* b1     = (const float*)d_in[17];
    const float* dw_w   = (const float*)d_in[18];
    const float* dw_b   = (const float*)d_in[19];
    const float* W2     = (const float*)d_in[20];
    const float* b2     = (const float*)d_in[21];

    float *xz, *xc, *xdb, *dt, *x2, *f1;
    bf16 *xnh, *xnl, *xch, *xcl, *yh, *yl, *f2h, *f2l;
    bf16 *winh, *winl, *wxh, *wxl, *woh, *wol, *w1h, *w1l, *w2h, *w2l;
    cudaGetSymbolAddress((void**)&xz,  g_xz);
    cudaGetSymbolAddress((void**)&xc,  g_xc);
    cudaGetSymbolAddress((void**)&xdb, g_xdb);
    cudaGetSymbolAddress((void**)&dt,  g_dt);
    cudaGetSymbolAddress((void**)&x2,  g_x2);
    cudaGetSymbolAddress((void**)&f1,  g_f1);
    cudaGetSymbolAddress((void**)&xnh, g_xnh);
    cudaGetSymbolAddress((void**)&xnl, g_xnl);
    cudaGetSymbolAddress((void**)&xch, g_xch);
    cudaGetSymbolAddress((void**)&xcl, g_xcl);
    cudaGetSymbolAddress((void**)&yh,  g_yh);
    cudaGetSymbolAddress((void**)&yl,  g_yl);
    cudaGetSymbolAddress((void**)&f2h, g_f2h);
    cudaGetSymbolAddress((void**)&f2l, g_f2l);
    cudaGetSymbolAddress((void**)&winh, g_winh);
    cudaGetSymbolAddress((void**)&winl, g_winl);
    cudaGetSymbolAddress((void**)&wxh,  g_wxh);
    cudaGetSymbolAddress((void**)&wxl,  g_wxl);
    cudaGetSymbolAddress((void**)&woh,  g_woh);
    cudaGetSymbolAddress((void**)&wol,  g_wol);
    cudaGetSymbolAddress((void**)&w1h,  g_w1h);
    cudaGetSymbolAddress((void**)&w1l,  g_w1l);
    cudaGetSymbolAddress((void**)&w2h,  g_w2h);
    cudaGetSymbolAddress((void**)&w2l,  g_w2l);

    // raise dynamic smem limit (idempotent)
    cudaFuncSetAttribute(bgemm_kernel<0>, cudaFuncAttributeMaxDynamicSharedMemorySize, SM_BYTES);
    cudaFuncSetAttribute(bgemm_kernel<1>, cudaFuncAttributeMaxDynamicSharedMemorySize, SM_BYTES);
    cudaFuncSetAttribute(bgemm_kernel<2>, cudaFuncAttributeMaxDynamicSharedMemorySize, SM_BYTES);
    cudaFuncSetAttribute(bgemm_kernel<3>, cudaFuncAttributeMaxDynamicSharedMemorySize, SM_BYTES);

    // 0) weight conversion (cheap, once per launch)
    wconv_kernel<<<(1536*384+255)/256, 256>>>(W_in,  winh, winl, 1536*384);
    wconv_pad_kernel<<<(XDBP*768+255)/256, 256>>>(W_xprj, wxh, wxl);
    wconv_kernel<<<(384*768+255)/256, 256>>>(W_out, woh, wol, 384*768);
    wconv_kernel<<<(1536*384+255)/256, 256>>>(W1,    w1h, w1l, 1536*384);
    wconv_kernel<<<(384*1536+255)/256, 256>>>(W2,    w2h, w2l, 384*1536);

    // 1) LN1 -> bf16 hi/lo
    ln_bf16_kernel<<<MROWS/8, 256>>>(x, gamma1, beta1, xnh, xnl);
    // 2) xz = xn @ W_in^T  (N=1536, K=384)
    { dim3 g(1536/64, MROWS/128);
      bgemm_kernel<0><<<g, 256, SM_BYTES>>>(xnh, xnl, winh, winl, xz, nullptr, nullptr, MROWS, 1536, DIMC); }
    // 3) xc = silu(conv1d(xr)) (+ bf16 copies)
    conv_silu_kernel<<<(MROWS*DIN)/256, 256>>>(xz, conv_w, conv_b, xc, xch, xcl);
    // 4) xdb = xc @ W_xproj^T  (N=192 padded, K=768)
    { dim3 g(XDBP/64, MROWS/128);
      bgemm_kernel<0><<<g, 256, SM_BYTES>>>(xch, xcl, wxh, wxl, xdb, nullptr, nullptr, MROWS, XDBP, DIN); }
    // 5) dt
    dt_kernel<<<MROWS, 256>>>(xdb, W_dt, b_dt, dt);
    // 6) scan -> y (bf16 hi/lo)
    scan_kernel<<<(BATCH*DIN)/4, 128>>>(dt, xc, xz, xdb, A_log, Dp, yh, yl);
    // 7) x2 = x + y @ W_out^T  (N=384, K=768)
    { dim3 g(DIMC/64, MROWS/128);
      bgemm_kernel<2><<<g, 256, SM_BYTES>>>(yh, yl, woh, wol, x2, nullptr, x, MROWS, DIMC, DIN); }
    // 8) LN2 -> bf16 hi/lo
    ln_bf16_kernel<<<MROWS/8, 256>>>(x2, gamma2, beta2, xnh, xnl);
    // 9) f1 = xn2 @ W1^T + b1  (N=1536, K=384)
    { dim3 g(HIDC/64, MROWS/128);
      bgemm_kernel<1><<<g, 256, SM_BYTES>>>(xnh, xnl, w1h, w1l, f1, b1, nullptr, MROWS, HIDC, DIMC); }
    // 10) f2 = gelu(dwconv3x3(f1)) (bf16 hi/lo)
    dwconv_gelu_kernel<<<(MROWS*HIDC)/256, 256>>>(f1, dw_w, dw_b, f2h, f2l);
    // 11) out = x2 + f2 @ W2^T + b2  (N=384, K=1536)
    { dim3 g(DIMC/64, MROWS/128);
      bgemm_kernel<3><<<g, 256, SM_BYTES>>>(f2h, f2l, w2h, w2l, (float*)d_out, b2, x2, MROWS, DIMC, HIDC); }
}

// round 9
// speedup vs baseline: 1.7381x; 1.3762x over previous
#include <cuda_runtime.h>
#include <cuda_bf16.h>
#include <cstdint>

#define BATCH  8
#define LTOK   4096
#define DIMC   384
#define DIN    768
#define DSTATE 64
#define DTRANK 24
#define HIDC   1536
#define MROWS  (BATCH*LTOK)   // 32768
#define XDBP   192            // padded xproj width (152 -> 192)

typedef __nv_bfloat16 bf16;

// ---------------- scratch (static device memory) ---------------------------
__device__ float g_xz [ (size_t)MROWS*1536 ];
__device__ float g_xc [ (size_t)MROWS*DIN  ];
__device__ float g_xdb[ (size_t)MROWS*XDBP ];
__device__ float g_x2 [ (size_t)MROWS*DIMC ];
__device__ float g_f1 [ (size_t)MROWS*HIDC ];

__device__ alignas(16) bf16 g_xnh[ (size_t)MROWS*DIMC ];
__device__ alignas(16) bf16 g_xnl[ (size_t)MROWS*DIMC ];
__device__ alignas(16) bf16 g_xch[ (size_t)MROWS*DIN  ];
__device__ alignas(16) bf16 g_xcl[ (size_t)MROWS*DIN  ];
__device__ alignas(16) bf16 g_yh [ (size_t)MROWS*DIN  ];
__device__ alignas(16) bf16 g_yl [ (size_t)MROWS*DIN  ];
__device__ alignas(16) bf16 g_f2h[ (size_t)MROWS*HIDC ];
__device__ alignas(16) bf16 g_f2l[ (size_t)MROWS*HIDC ];

// weights hi/lo
__device__ alignas(16) bf16 g_winh[1536*384], g_winl[1536*384];
__device__ alignas(16) bf16 g_wxh [XDBP*768], g_wxl [XDBP*768];
__device__ alignas(16) bf16 g_woh [384*768],  g_wol [384*768];
__device__ alignas(16) bf16 g_w1h [1536*384], g_w1l [1536*384];
__device__ alignas(16) bf16 g_w2h [384*1536], g_w2l [384*1536];

__device__ __forceinline__ void split_bf16(float v, bf16& h, bf16& l) {
    h = __float2bfloat16(v);
    l = __float2bfloat16(v - __bfloat162float(h));
}

// ---------------- weight fp32 -> bf16 hi/lo --------------------------------
__global__ void wconv_kernel(const float* __restrict__ W, bf16* __restrict__ wh,
                             bf16* __restrict__ wl, int n) {
    int i = blockIdx.x * 256 + threadIdx.x;
    if (i < n) { bf16 h, l; split_bf16(W[i], h, l); wh[i] = h; wl[i] = l; }
}
// two same-size weights in one launch (keeps launch count aligned for ncu -s 5)
__global__ void wconv2_kernel(const float* __restrict__ Wa, bf16* __restrict__ wah,
                              bf16* __restrict__ wal,
                              const float* __restrict__ Wb, bf16* __restrict__ wbh,
                              bf16* __restrict__ wbl, int n) {
    int i = blockIdx.x * 256 + threadIdx.x;
    if (i < n) {
        bf16 h, l;
        split_bf16(Wa[i], h, l); wah[i] = h; wal[i] = l;
        split_bf16(Wb[i], h, l); wbh[i] = h; wbl[i] = l;
    }
}
// padded xproj weight: rows 152..191 zero
__global__ void wconv_pad_kernel(const float* __restrict__ W, bf16* __restrict__ wh,
                                 bf16* __restrict__ wl) {
    int i = blockIdx.x * 256 + threadIdx.x;   // over XDBP*768
    if (i >= XDBP*768) return;
    int row = i / 768, col = i % 768;
    float v = (row < 152) ? W[row*768 + col] : 0.f;
    bf16 h, l; split_bf16(v, h, l); wh[i] = h; wl[i] = l;
}

// ---------------- LayerNorm -> bf16 hi/lo ----------------------------------
__global__ void ln_bf16_kernel(const float* __restrict__ x, const float* __restrict__ g,
                               const float* __restrict__ b, bf16* __restrict__ oh,
                               bf16* __restrict__ ol) {
    int row  = blockIdx.x * 8 + (threadIdx.x >> 5);
    int lane = threadIdx.x & 31;
    const float* xr = x + (size_t)row * DIMC;
    float v[12];
    float s = 0.f;
#pragma unroll
    for (int i = 0; i < 12; i++) { v[i] = xr[lane + 32*i]; s += v[i]; }
#pragma unroll
    for (int o = 16; o; o >>= 1) s += __shfl_xor_sync(~0u, s, o);
    float mu = s * (1.0f/DIMC);
    float q = 0.f;
#pragma unroll
    for (int i = 0; i < 12; i++) { float d = v[i]-mu; q += d*d; }
#pragma unroll
    for (int o = 16; o; o >>= 1) q += __shfl_xor_sync(~0u, q, o);
    float rs = rsqrtf(q*(1.0f/DIMC) + 1e-5f);
#pragma unroll
    for (int i = 0; i < 12; i++) {
        int c = lane + 32*i;
        float o = (v[i]-mu)*rs*g[c] + b[c];
        bf16 h, l; split_bf16(o, h, l);
        oh[(size_t)row*DIMC + c] = h;
        ol[(size_t)row*DIMC + c] = l;
    }
}

// =====================================================================
// bf16 split GEMM: C[M,N] = (Ah+Al)[M,K] @ (Bh+Bl)[N,K]^T (3-pass),
// cp.async double-buffered. BM=128, BN=64, BK=32. 256 thr = 8 warps (2x4).
// EPI: bit0 = +bias[col], bit1 = +res[row*N+col]
// =====================================================================
#define AST 40          // smem row stride in halves (80B)
#define STG 15360       // halves per stage
#define SM_BYTES (2*STG*2)

__device__ __forceinline__ void cp16(uint32_t dst, const void* src) {
    asm volatile("cp.async.cg.shared.global [%0], [%1], 16;" :: "r"(dst), "l"(src));
}
__device__ __forceinline__ void ldsm4(uint32_t r[4], uint32_t addr) {
    asm volatile("ldmatrix.sync.aligned.m8n8.x4.shared.b16 {%0,%1,%2,%3}, [%4];"
        : "=r"(r[0]), "=r"(r[1]), "=r"(r[2]), "=r"(r[3]) : "r"(addr));
}
__device__ __forceinline__ void mma16816(float c[4], const uint32_t a[4],
                                         uint32_t b0, uint32_t b1) {
    asm volatile("mma.sync.aligned.m16n8k16.row.col.f32.bf16.bf16.f32 "
        "{%0,%1,%2,%3}, {%4,%5,%6,%7}, {%8,%9}, {%0,%1,%2,%3};"
        : "+f"(c[0]), "+f"(c[1]), "+f"(c[2]), "+f"(c[3])
        : "r"(a[0]), "r"(a[1]), "r"(a[2]), "r"(a[3]), "r"(b0), "r"(b1));
}

template<int EPI>
__global__ void __launch_bounds__(256, 2)
bgemm_kernel(const bf16* __restrict__ Ah, const bf16* __restrict__ Al,
             const bf16* __restrict__ Bh, const bf16* __restrict__ Bl,
             float* __restrict__ C, const float* __restrict__ bias,
             const float* __restrict__ res, int M, int N, int K) {
    extern __shared__ bf16 sm[];
    const uint32_t base = (uint32_t)__cvta_generic_to_shared(sm);

    const int tid  = threadIdx.x;
    const int lane = tid & 31, warp = tid >> 5;
    const int wm = warp >> 2, wn = warp & 3;
    const int m0 = blockIdx.y * 128;
    const int n0 = blockIdx.x * 64;

    float acc[4][2][4];
#pragma unroll
    for (int i = 0; i < 4; i++)
#pragma unroll
        for (int j = 0; j < 2; j++)
#pragma unroll
            for (int t = 0; t < 4; t++) acc[i][j][t] = 0.f;

    const int iters = K / 32;

    const int ra0 = (tid*2) >> 2,  ka0 = (tid*2) & 3;
    const int ra1 = (tid*2+1) >> 2, ka1 = (tid*2+1) & 3;
    const int rb  = tid >> 2,       kb  = tid & 3;

    auto issue = [&](int it, int s) {
        const int k0 = it * 32;
        uint32_t sb = base + (uint32_t)(s*STG)*2;
        cp16(sb + (ra0*AST + ka0*8)*2,        Ah + (size_t)(m0+ra0)*K + k0 + ka0*8);
        cp16(sb + (ra1*AST + ka1*8)*2,        Ah + (size_t)(m0+ra1)*K + k0 + ka1*8);
        cp16(sb + (5120 + ra0*AST + ka0*8)*2, Al + (size_t)(m0+ra0)*K + k0 + ka0*8);
        cp16(sb + (5120 + ra1*AST + ka1*8)*2, Al + (size_t)(m0+ra1)*K + k0 + ka1*8);
        cp16(sb + (10240 + rb*AST + kb*8)*2,  Bh + (size_t)(n0+rb)*K + k0 + kb*8);
        cp16(sb + (12800 + rb*AST + kb*8)*2,  Bl + (size_t)(n0+rb)*K + k0 + kb*8);
        asm volatile("cp.async.commit_group;");
    };

    issue(0, 0);

    for (int it = 0; it < iters; ++it) {
        if (it + 1 < iters) {
            issue(it + 1, (it + 1) & 1);
            asm volatile("cp.async.wait_group 1;");
        } else {
            asm volatile("cp.async.wait_group 0;");
        }
        __syncthreads();

        const int s = it & 1;
        const uint32_t bAh = base + (uint32_t)(s*STG)*2;
        const uint32_t bAl = bAh + 5120*2;
        const uint32_t bBh = bAh + 10240*2;
        const uint32_t bBl = bAh + 12800*2;

#pragma unroll
        for (int st = 0; st < 2; st++) {
            const int kk = st * 16;
            uint32_t Ahf[4][4], Alf[4][4], Bhf[4], Blf[4];
            const int arow = (lane & 15);
            const int acol = kk + ((lane >> 4) * 8);
#pragma unroll
            for (int mf = 0; mf < 4; mf++) {
                uint32_t off = (uint32_t)((wm*64 + mf*16 + arow) * AST + acol) * 2;
                ldsm4(Ahf[mf], bAh + off);
                ldsm4(Alf[mf], bAl + off);
            }
            {
                const int brow = wn*16 + (lane & 7) + ((lane >> 4) * 8);
                const int bcol = kk + (((lane >> 3) & 1) * 8);
                uint32_t off = (uint32_t)(brow * AST + bcol) * 2;
                ldsm4(Bhf, bBh + off);
                ldsm4(Blf, bBl + off);
            }
#pragma unroll
            for (int mf = 0; mf < 4; mf++) {
                mma16816(acc[mf][0], Ahf[mf], Bhf[0], Bhf[1]);
                mma16816(acc[mf][1], Ahf[mf], Bhf[2], Bhf[3]);
                mma16816(acc[mf][0], Ahf[mf], Blf[0], Blf[1]);
                mma16816(acc[mf][1], Ahf[mf], Blf[2], Blf[3]);
                mma16816(acc[mf][0], Alf[mf], Bhf[0], Bhf[1]);
                mma16816(acc[mf][1], Alf[mf], Bhf[2], Bhf[3]);
            }
        }
        __syncthreads();
    }

    const int g = lane >> 2, tc = lane & 3;
#pragma unroll
    for (int mf = 0; mf < 4; mf++) {
#pragma unroll
        for (int nf = 0; nf < 2; nf++) {
            int col = n0 + wn*16 + nf*8 + tc*2;
            float b0 = 0.f, b1 = 0.f;
            if (EPI & 1) { b0 = bias[col]; b1 = bias[col+1]; }
#pragma unroll
            for (int half = 0; half < 2; half++) {
                int row = m0 + wm*64 + mf*16 + g + half*8;
                float v0 = acc[mf][nf][half*2]   + b0;
                float v1 = acc[mf][nf][half*2+1] + b1;
                if (EPI & 2) {
                    const float2 r = *(const float2*)(res + (size_t)row*N + col);
                    v0 += r.x; v1 += r.y;
                }
                *(float2*)(C + (size_t)row*N + col) = make_float2(v0, v1);
            }
        }
    }
}

// ---------------- causal depthwise conv1d (width 4) + SiLU ------------------
__global__ void conv_silu_kernel(const float* __restrict__ xz, const float* __restrict__ cw,
                                 const float* __restrict__ cb, float* __restrict__ xc,
                                 bf16* __restrict__ xch, bf16* __restrict__ xcl) {
    int idx = blockIdx.x * 256 + threadIdx.x;
    int d   = idx % DIN;
    int row = idx / DIN;
    int t   = row % LTOK;
    float acc = cb[d];
#pragma unroll
    for (int k = 0; k < 4; k++) {
        int tt = t + k - 3;
        if (tt >= 0)
            acc += xz[(size_t)(row + k - 3)*1536 + d] * cw[d*4 + k];
    }
    float s = acc / (1.f + __expf(-acc));
    xc[idx] = s;
    bf16 h, l; split_bf16(s, h, l);
    xch[idx] = h; xcl[idx] = l;
}

// ---------------- fused dt + selective scan ---------------------------------
// Block: 256 threads = 8 warps = 8 channels of one batch. Chunks of 32 steps.
// Stages xdb cols 0..159 (dt-in | B | C), xc, z in smem; computes dt in-block.
#define SCH 8
#define STT 32
__global__ void __launch_bounds__(256)
scan_kernel(const float* __restrict__ xc, const float* __restrict__ xz,
            const float* __restrict__ xdb,
            const float* __restrict__ Wdt, const float* __restrict__ bdt,
            const float* __restrict__ A_log, const float* __restrict__ Dp,
            bf16* __restrict__ yh, bf16* __restrict__ yl) {
    __shared__ float s_xdb[STT][161];   // cols 0..159 of xdb row (pad 161, conflict-free)
    __shared__ float s_dt[STT][SCH];
    __shared__ float s_x [STT][SCH];
    __shared__ float s_z [STT][SCH];
    __shared__ float s_w [SCH][24];

    const int tid  = threadIdx.x;
    const int warp = tid >> 5, lane = tid & 31;
    const int b  = blockIdx.x / (DIN/SCH);
    const int d0 = (blockIdx.x % (DIN/SCH)) * SCH;
    const int d  = d0 + warp;

    if (tid < SCH*24) s_w[tid/24][tid%24] = Wdt[(d0 + tid/24)*24 + (tid%24)];
    const float bdt_c = bdt[d];
    const float A1 = -expf(A_log[d*DSTATE + lane]);
    const float A2 = -expf(A_log[d*DSTATE + lane + 32]);
    const float Dpd = Dp[d];
    float h1 = 0.f, h2 = 0.f;
    const size_t rbase = (size_t)b * LTOK;

    for (int t0 = 0; t0 < LTOK; t0 += STT) {
        __syncthreads();   // buffer reuse guard
        // stage xdb rows: LDG.128, then 4 scalar STS (stride 161 is not
        // 16B-aligned per row, so vector STS would trap on odd rows)
        for (int i = tid; i < STT*40; i += 256) {
            int row = i / 40, q = i % 40;
            float4 v = *(const float4*)(xdb + (rbase + t0 + row)*XDBP + q*4);
            s_xdb[row][q*4+0] = v.x;
            s_xdb[row][q*4+1] = v.y;
            s_xdb[row][q*4+2] = v.z;
            s_xdb[row][q*4+3] = v.w;
        }
        // stage x and z (stride 8 floats = 32B, float4 OK)
        if (tid < 64) {
            int row = tid >> 1, q = tid & 1;
            *(float4*)&s_x[row][q*4] =
                *(const float4*)(xc + (rbase + t0 + row)*DIN + d0 + q*4);
        } else if (tid < 128) {
            int i = tid - 64, row = i >> 1, q = i & 1;
            *(float4*)&s_z[row][q*4] =
                *(const float4*)(xz + (rbase + t0 + row)*1536 + DIN + d0 + q*4);
        }
        __syncthreads();
        // dt: warp = channel, lane = timestep
        {
            float acc = bdt_c;
#pragma unroll
            for (int k = 0; k < 24; k++) acc = fmaf(s_xdb[lane][k], s_w[warp][k], acc);
            s_dt[lane][warp] = (acc > 20.f) ? acc : log1pf(__expf(acc));
        }
        __syncthreads();
        // scan 32 steps
        for (int tt = 0; tt < STT; tt++) {
            float dtv = s_dt[tt][warp];
            float xv  = s_x[tt][warp];
            float B1 = s_xdb[tt][24+lane], B2 = s_xdb[tt][56+lane];
            float C1 = s_xdb[tt][88+lane], C2 = s_xdb[tt][120+lane];
            float dA1 = __expf(dtv*A1), dA2 = __expf(dtv*A2);
            float dtx = dtv * xv;
            h1 = h1*dA1 + dtx*B1;
            h2 = h2*dA2 + dtx*B2;
            float p = h1*C1 + h2*C2;
#pragma unroll
            for (int o = 16; o; o >>= 1) p += __shfl_xor_sync(~0u, p, o);
            if (lane == 0) {
                float zv = s_z[tt][warp];
                float yv = (p + xv*Dpd) * (zv / (1.f + __expf(-zv)));
                bf16 hh, ll; split_bf16(yv, hh, ll);
                size_t r = rbase + t0 + tt;
                yh[r*DIN + d] = hh; yl[r*DIN + d] = ll;
            }
        }
    }
}

// ---------------- 3x3 depthwise conv on 64x64 grid + exact GELU -------------
__global__ void dwconv_gelu_kernel(const float* __restrict__ f, const float* __restrict__ w,
                                   const float* __restrict__ bias,
                                   bf16* __restrict__ oh, bf16* __restrict__ ol) {
    int idx = blockIdx.x * 256 + threadIdx.x;
    int d = idx % HIDC;
    int n = (idx / HIDC) % LTOK;
    int b = idx / (HIDC * LTOK);
    int r = n >> 6, c = n & 63;
    float acc = bias[d];
#pragma unroll
    for (int i = 0; i < 3; i++) {
        int rr = r + i - 1;
        if ((unsigned)rr < 64u) {
#pragma unroll
            for (int j = 0; j < 3; j++) {
                int cc = c + j - 1;
                if ((unsigned)cc < 64u)
                    acc += f[((size_t)b*LTOK + rr*64 + cc)*HIDC + d] * w[d*9 + i*3 + j];
            }
        }
    }
    float g = 0.5f * acc * (1.f + erff(acc * 0.7071067811865476f));
    bf16 h, l; split_bf16(g, h, l);
    oh[idx] = h; ol[idx] = l;
}

// ---------------- launch --------------------------------------------------
extern "C" void kernel_launch(void* const* d_in, const int* in_sizes, int n_in,
                              void* d_out, int out_size) {
    const float* x      = (const float*)d_in[0];
    const float* gamma1 = (const float*)d_in[3];
    const float* beta1  = (const float*)d_in[4];
    const float* W_in   = (const float*)d_in[5];
    const float* conv_w = (const float*)d_in[6];
    const float* conv_b = (const float*)d_in[7];
    const float* W_xprj = (const float*)d_in[8];
    const float* W_dt   = (const float*)d_in[9];
    const float* b_dt   = (const float*)d_in[10];
    const float* A_log  = (const float*)d_in[11];
    const float* Dp     = (const float*)d_in[12];
    const float* W_out  = (const float*)d_in[13];
    const float* gamma2 = (const float*)d_in[14];
    const float* beta2  = (const float*)d_in[15];
    const float* W1     = (const float*)d_in[16];
    const float* b1     = (const float*)d_in[17];
    const float* dw_w   = (const float*)d_in[18];
    const float* dw_b   = (const float*)d_in[19];
    const float* W2     = (const float*)d_in[20];
    const float* b2     = (const float*)d_in[21];

    float *xz, *xc, *xdb, *x2, *f1;
    bf16 *xnh, *xnl, *xch, *xcl, *yh, *yl, *f2h, *f2l;
    bf16 *winh, *winl, *wxh, *wxl, *woh, *wol, *w1h, *w1l, *w2h, *w2l;
    cudaGetSymbolAddress((void**)&xz,  g_xz);
    cudaGetSymbolAddress((void**)&xc,  g_xc);
    cudaGetSymbolAddress((void**)&xdb, g_xdb);
    cudaGetSymbolAddress((void**)&x2,  g_x2);
    cudaGetSymbolAddress((void**)&f1,  g_f1);
    cudaGetSymbolAddress((void**)&xnh, g_xnh);
    cudaGetSymbolAddress((void**)&xnl, g_xnl);
    cudaGetSymbolAddress((void**)&xch, g_xch);
    cudaGetSymbolAddress((void**)&xcl, g_xcl);
    cudaGetSymbolAddress((void**)&yh,  g_yh);
    cudaGetSymbolAddress((void**)&yl,  g_yl);
    cudaGetSymbolAddress((void**)&f2h, g_f2h);
    cudaGetSymbolAddress((void**)&f2l, g_f2l);
    cudaGetSymbolAddress((void**)&winh, g_winh);
    cudaGetSymbolAddress((void**)&winl, g_winl);
    cudaGetSymbolAddress((void**)&wxh,  g_wxh);
    cudaGetSymbolAddress((void**)&wxl,  g_wxl);
    cudaGetSymbolAddress((void**)&woh,  g_woh);
    cudaGetSymbolAddress((void**)&wol,  g_wol);
    cudaGetSymbolAddress((void**)&w1h,  g_w1h);
    cudaGetSymbolAddress((void**)&w1l,  g_w1l);
    cudaGetSymbolAddress((void**)&w2h,  g_w2h);
    cudaGetSymbolAddress((void**)&w2l,  g_w2l);

    cudaFuncSetAttribute(bgemm_kernel<0>, cudaFuncAttributeMaxDynamicSharedMemorySize, SM_BYTES);
    cudaFuncSetAttribute(bgemm_kernel<1>, cudaFuncAttributeMaxDynamicSharedMemorySize, SM_BYTES);
    cudaFuncSetAttribute(bgemm_kernel<2>, cudaFuncAttributeMaxDynamicSharedMemorySize, SM_BYTES);
    cudaFuncSetAttribute(bgemm_kernel<3>, cudaFuncAttributeMaxDynamicSharedMemorySize, SM_BYTES);

    // launches 0-3: weight conversion (W1+W2 merged so big GEMM lands at ncu index 5)
    wconv_kernel<<<(1536*384+255)/256, 256>>>(W_in,  winh, winl, 1536*384);
    wconv_pad_kernel<<<(XDBP*768+255)/256, 256>>>(W_xprj, wxh, wxl);
    wconv_kernel<<<(384*768+255)/256, 256>>>(W_out, woh, wol, 384*768);
    wconv2_kernel<<<(1536*384+255)/256, 256>>>(W1, w1h, w1l, W2, w2h, w2l, 1536*384);

    // 4) LN1 -> bf16 hi/lo
    ln_bf16_kernel<<<MROWS/8, 256>>>(x, gamma1, beta1, xnh, xnl);
    // 5) xz = xn @ W_in^T  (N=1536, K=384)   <-- ncu -s 5 captures this
    { dim3 g(1536/64, MROWS/128);
      bgemm_kernel<0><<<g, 256, SM_BYTES>>>(xnh, xnl, winh, winl, xz, nullptr, nullptr, MROWS, 1536, DIMC); }
    // 6) xc = silu(conv1d(xr)) (+ bf16 copies)
    conv_silu_kernel<<<(MROWS*DIN)/256, 256>>>(xz, conv_w, conv_b, xc, xch, xcl);
    // 7) xdb = xc @ W_xproj^T  (N=192 padded, K=768)
    { dim3 g(XDBP/64, MROWS/128);
      bgemm_kernel<0><<<g, 256, SM_BYTES>>>(xch, xcl, wxh, wxl, xdb, nullptr, nullptr, MROWS, XDBP, DIN); }
    // 8) fused dt + scan -> y (bf16 hi/lo)
    scan_kernel<<<BATCH*(DIN/SCH), 256>>>(xc, xz, xdb, W_dt, b_dt, A_log, Dp, yh, yl);
    // 9) x2 = x + y @ W_out^T  (N=384, K=768)
    { dim3 g(DIMC/64, MROWS/128);
      bgemm_kernel<2><<<g, 256, SM_BYTES>>>(yh, yl, woh, wol, x2, nullptr, x, MROWS, DIMC, DIN); }
    // 10) LN2 -> bf16 hi/lo
    ln_bf16_kernel<<<MROWS/8, 256>>>(x2, gamma2, beta2, xnh, xnl);
    // 11) f1 = xn2 @ W1^T + b1  (N=1536, K=384)
    { dim3 g(HIDC/64, MROWS/128);
      bgemm_kernel<1><<<g, 256, SM_BYTES>>>(xnh, xnl, w1h, w1l, f1, b1, nullptr, MROWS, HIDC, DIMC); }
    // 12) f2 = gelu(dwconv3x3(f1)) (bf16 hi/lo)
    dwconv_gelu_kernel<<<(MROWS*HIDC)/256, 256>>>(f1, dw_w, dw_b, f2h, f2l);
    // 13) out = x2 + f2 @ W2^T + b2  (N=384, K=1536)
    { dim3 g(DIMC/64, MROWS/128);
      bgemm_kernel<3><<<g, 256, SM_BYTES>>>(f2h, f2l, w2h, w2l, (float*)d_out, b2, x2, MROWS, DIMC, HIDC); }
}